// round 1
// baseline (speedup 1.0000x reference)
#include <cuda_runtime.h>
#include <math.h>
#include <stdint.h>

// Problem constants
#define BB 4
#define NN 2048
#define CC 1024
#define HH 16
#define DD 64
#define MTOK (BB * NN)      // 8192 tokens
#define QKVN (3 * CC)       // 3072

// Scratch (allocation-free rule: __device__ globals)
__device__ float g_qkv[(size_t)MTOK * QKVN];  // [8192][3072]  (Q|K|V per token)
__device__ float g_att[(size_t)MTOK * CC];    // [8192][1024]  attention output (merged heads)

// ---------------------------------------------------------------------------
// SGEMM: C[M, Nc] = A[M, K] @ W[Nc, K]^T  (+ optional bias[Nc])
// 128x128 tile, BK=8, 256 threads, 8x8 per thread.
// M, Nc multiples of 128; K multiple of 8. (Holds for all our shapes.)
// ---------------------------------------------------------------------------
__global__ __launch_bounds__(256) void gemm_xWt_kernel(
    const float* __restrict__ A, const float* __restrict__ W,
    const float* __restrict__ bias, float* __restrict__ Cmat,
    int M, int Nc, int K)
{
    __shared__ float As[8][128];   // [k][m]
    __shared__ float Bs[8][128];   // [k][n]

    const int t  = threadIdx.x;
    const int tx = t & 15;         // 0..15 -> n direction
    const int ty = t >> 4;         // 0..15 -> m direction
    const int bm = blockIdx.y * 128;
    const int bn = blockIdx.x * 128;

    const int lrow = t >> 1;          // 0..127
    const int lk   = (t & 1) * 4;     // 0 or 4

    const float* Aptr = A + (size_t)(bm + lrow) * K + lk;
    const float* Wptr = W + (size_t)(bn + lrow) * K + lk;

    float acc[8][8];
    #pragma unroll
    for (int i = 0; i < 8; i++)
        #pragma unroll
        for (int j = 0; j < 8; j++) acc[i][j] = 0.f;

    for (int kb = 0; kb < K; kb += 8) {
        float4 av = *(const float4*)(Aptr + kb);
        float4 wv = *(const float4*)(Wptr + kb);
        As[lk + 0][lrow] = av.x; As[lk + 1][lrow] = av.y;
        As[lk + 2][lrow] = av.z; As[lk + 3][lrow] = av.w;
        Bs[lk + 0][lrow] = wv.x; Bs[lk + 1][lrow] = wv.y;
        Bs[lk + 2][lrow] = wv.z; Bs[lk + 3][lrow] = wv.w;
        __syncthreads();

        #pragma unroll
        for (int k = 0; k < 8; k++) {
            float4 a0 = *(const float4*)&As[k][ty * 8];
            float4 a1 = *(const float4*)&As[k][ty * 8 + 4];
            float4 b0 = *(const float4*)&Bs[k][tx * 8];
            float4 b1 = *(const float4*)&Bs[k][tx * 8 + 4];
            float ar[8] = {a0.x, a0.y, a0.z, a0.w, a1.x, a1.y, a1.z, a1.w};
            float br[8] = {b0.x, b0.y, b0.z, b0.w, b1.x, b1.y, b1.z, b1.w};
            #pragma unroll
            for (int i = 0; i < 8; i++)
                #pragma unroll
                for (int j = 0; j < 8; j++)
                    acc[i][j] = fmaf(ar[i], br[j], acc[i][j]);
        }
        __syncthreads();
    }

    float bv[8];
    if (bias) {
        float4 b0 = *(const float4*)(bias + bn + tx * 8);
        float4 b1 = *(const float4*)(bias + bn + tx * 8 + 4);
        bv[0]=b0.x; bv[1]=b0.y; bv[2]=b0.z; bv[3]=b0.w;
        bv[4]=b1.x; bv[5]=b1.y; bv[6]=b1.z; bv[7]=b1.w;
    } else {
        #pragma unroll
        for (int j = 0; j < 8; j++) bv[j] = 0.f;
    }

    #pragma unroll
    for (int i = 0; i < 8; i++) {
        float* crow = Cmat + (size_t)(bm + ty * 8 + i) * Nc + bn + tx * 8;
        float4 v0 = make_float4(acc[i][0] + bv[0], acc[i][1] + bv[1],
                                acc[i][2] + bv[2], acc[i][3] + bv[3]);
        float4 v1 = make_float4(acc[i][4] + bv[4], acc[i][5] + bv[5],
                                acc[i][6] + bv[6], acc[i][7] + bv[7]);
        *(float4*)crow       = v0;
        *(float4*)(crow + 4) = v1;
    }
}

// ---------------------------------------------------------------------------
// Flash attention, fp32. One block = (64 q rows) x (one b,h).
// 256 threads as 16(tx: d/kcol) x 16(ty: qrow) grid, 4x4 micro-tiles.
// smem: Qt[d][q] (scaled by 1/sqrt(D)), KP[d][kcol] (reused for P[kcol][q]),
//       Vs[kcol][d].  Exactly 48 KB static.
// ---------------------------------------------------------------------------
__global__ __launch_bounds__(256) void attn_kernel()
{
    __shared__ float Qt[64][64];   // [d][q]
    __shared__ float KP[64][64];   // K: [d][j]; later P: [j][q]
    __shared__ float Vs[64][64];   // [j][d]

    const int t  = threadIdx.x;
    const int tx = t & 15;
    const int ty = t >> 4;
    const int qb = blockIdx.x * 64;
    const int h  = blockIdx.y;
    const int b  = blockIdx.z;

    const int lane4 = t & 3;
    const int row   = t >> 2;   // 0..63

    // Load Q tile transposed, folding in the softmax scale (1/sqrt(64) = 0.125)
    {
        const float* qrow = g_qkv + (size_t)(b * NN + qb + row) * QKVN + h * DD;
        #pragma unroll
        for (int ii = 0; ii < 4; ii++) {
            int d0 = (lane4 + 4 * ii) * 4;
            float4 v = *(const float4*)(qrow + d0);
            Qt[d0 + 0][row] = v.x * 0.125f;
            Qt[d0 + 1][row] = v.y * 0.125f;
            Qt[d0 + 2][row] = v.z * 0.125f;
            Qt[d0 + 3][row] = v.w * 0.125f;
        }
    }

    float acc[4][4];
    #pragma unroll
    for (int i = 0; i < 4; i++)
        #pragma unroll
        for (int j = 0; j < 4; j++) acc[i][j] = 0.f;
    float mrow[4] = {-INFINITY, -INFINITY, -INFINITY, -INFINITY};
    float lrow[4] = {0.f, 0.f, 0.f, 0.f};

    for (int kb = 0; kb < NN; kb += 64) {
        // ---- load K (transposed) and V tiles ----
        {
            const float* krow = g_qkv + (size_t)(b * NN + kb + row) * QKVN + CC + h * DD;
            #pragma unroll
            for (int ii = 0; ii < 4; ii++) {
                int d0 = (lane4 + 4 * ii) * 4;
                float4 v = *(const float4*)(krow + d0);
                KP[d0 + 0][row] = v.x;
                KP[d0 + 1][row] = v.y;
                KP[d0 + 2][row] = v.z;
                KP[d0 + 3][row] = v.w;
            }
            #pragma unroll
            for (int ii = 0; ii < 4; ii++) {
                int flat4 = t + ii * 256;           // 0..1023
                int vr = flat4 >> 4;                // 0..63
                int c4 = (flat4 & 15) * 4;
                const float* vsrc = g_qkv + (size_t)(b * NN + kb + vr) * QKVN
                                    + 2 * CC + h * DD + c4;
                *(float4*)&Vs[vr][c4] = *(const float4*)vsrc;
            }
        }
        __syncthreads();

        // ---- S = Q K^T (scaled), 4x4 per thread ----
        float s[4][4];
        #pragma unroll
        for (int i = 0; i < 4; i++)
            #pragma unroll
            for (int j = 0; j < 4; j++) s[i][j] = 0.f;

        #pragma unroll 8
        for (int d = 0; d < 64; d++) {
            float4 qv = *(const float4*)&Qt[d][ty * 4];
            float4 kv = *(const float4*)&KP[d][tx * 4];
            float qa[4] = {qv.x, qv.y, qv.z, qv.w};
            float ka[4] = {kv.x, kv.y, kv.z, kv.w};
            #pragma unroll
            for (int i = 0; i < 4; i++)
                #pragma unroll
                for (int j = 0; j < 4; j++)
                    s[i][j] = fmaf(qa[i], ka[j], s[i][j]);
        }

        // ---- online softmax (rows split across 16 lanes: tx of same half-warp) ----
        #pragma unroll
        for (int i = 0; i < 4; i++) {
            float mt = fmaxf(fmaxf(s[i][0], s[i][1]), fmaxf(s[i][2], s[i][3]));
            #pragma unroll
            for (int off = 1; off < 16; off <<= 1)
                mt = fmaxf(mt, __shfl_xor_sync(0xffffffffu, mt, off));
            float mnew = fmaxf(mrow[i], mt);
            float corr = __expf(mrow[i] - mnew);
            mrow[i] = mnew;
            float ls = 0.f;
            #pragma unroll
            for (int j = 0; j < 4; j++) {
                s[i][j] = __expf(s[i][j] - mnew);
                ls += s[i][j];
            }
            #pragma unroll
            for (int off = 1; off < 16; off <<= 1)
                ls += __shfl_xor_sync(0xffffffffu, ls, off);
            lrow[i] = lrow[i] * corr + ls;
            #pragma unroll
            for (int j = 0; j < 4; j++) acc[i][j] *= corr;
        }

        __syncthreads();   // everyone done reading K from KP

        // ---- store P transposed into KP: P[j][q] ----
        #pragma unroll
        for (int jj = 0; jj < 4; jj++) {
            float4 pv = make_float4(s[0][jj], s[1][jj], s[2][jj], s[3][jj]);
            *(float4*)&KP[tx * 4 + jj][ty * 4] = pv;
        }
        __syncthreads();

        // ---- acc += P @ V ----
        #pragma unroll 4
        for (int j = 0; j < 64; j++) {
            float4 pv = *(const float4*)&KP[j][ty * 4];
            float4 vv = *(const float4*)&Vs[j][tx * 4];
            float pa[4] = {pv.x, pv.y, pv.z, pv.w};
            float va[4] = {vv.x, vv.y, vv.z, vv.w};
            #pragma unroll
            for (int i = 0; i < 4; i++)
                #pragma unroll
                for (int c = 0; c < 4; c++)
                    acc[i][c] = fmaf(pa[i], va[c], acc[i][c]);
        }
        __syncthreads();   // safe to overwrite KP/Vs next iteration
    }

    // ---- normalize and write out: g_att[b, q, h*D + d] ----
    #pragma unroll
    for (int i = 0; i < 4; i++) {
        float inv = 1.f / lrow[i];
        float* orow = g_att + (size_t)(b * NN + qb + ty * 4 + i) * CC + h * DD + tx * 4;
        float4 ov = make_float4(acc[i][0] * inv, acc[i][1] * inv,
                                acc[i][2] * inv, acc[i][3] * inv);
        *(float4*)orow = ov;
    }
}

// ---------------------------------------------------------------------------
// Launch
// ---------------------------------------------------------------------------
extern "C" void kernel_launch(void* const* d_in, const int* in_sizes, int n_in,
                              void* d_out, int out_size)
{
    const float* x     = (const float*)d_in[0];   // [4,2048,1024]
    const float* Wqkv  = (const float*)d_in[1];   // [3072,1024]
    const float* Wproj = (const float*)d_in[2];   // [1024,1024]
    const float* bproj = (const float*)d_in[3];   // [1024]
    float* out = (float*)d_out;                   // [4,2048,1024]

    float* qkv_ptr = nullptr;
    float* att_ptr = nullptr;
    cudaGetSymbolAddress((void**)&qkv_ptr, g_qkv);
    cudaGetSymbolAddress((void**)&att_ptr, g_att);

    // 1) QKV projection: [8192,1024] @ [1024,3072] -> g_qkv
    {
        dim3 grid(QKVN / 128, MTOK / 128);
        gemm_xWt_kernel<<<grid, 256>>>(x, Wqkv, nullptr, qkv_ptr, MTOK, QKVN, CC);
    }

    // 2) Attention per (b,h), 64 q rows per block
    {
        dim3 grid(NN / 64, HH, BB);
        attn_kernel<<<grid, 256>>>();
    }

    // 3) Output projection with bias: [8192,1024] @ [1024,1024] + b -> out
    {
        dim3 grid(CC / 128, MTOK / 128);
        gemm_xWt_kernel<<<grid, 256>>>(att_ptr, Wproj, bproj, out, MTOK, CC, CC);
    }
}

// round 2
// speedup vs baseline: 2.7513x; 2.7513x over previous
#include <cuda_runtime.h>
#include <math.h>
#include <stdint.h>

#define BB 4
#define NN 2048
#define CC 1024
#define HH 16
#define DD 64
#define MTOK (BB * NN)      // 8192
#define QKVN (3 * CC)       // 3072

__device__ float g_qkv[(size_t)MTOK * QKVN];  // Q|K|V per token
__device__ float g_att[(size_t)MTOK * CC];    // merged-head attention out

// ---------------- helpers ----------------
__device__ __forceinline__ uint32_t f2tf(float f) {
    uint32_t u;
    asm("cvt.rna.tf32.f32 %0, %1;" : "=r"(u) : "f"(f));
    return u;
}
__device__ __forceinline__ float ex2(float x) {
    float y;
    asm("ex2.approx.ftz.f32 %0, %1;" : "=f"(y) : "f"(x));
    return y;
}
// D += A(16x8,row) * B(8x8,col); tf32 inputs, f32 accum
__device__ __forceinline__ void mma8(float* c, const uint32_t* a, const uint32_t* b) {
    asm("mma.sync.aligned.m16n8k8.row.col.f32.tf32.tf32.f32 "
        "{%0,%1,%2,%3}, {%4,%5,%6,%7}, {%8,%9}, {%0,%1,%2,%3};"
        : "+f"(c[0]), "+f"(c[1]), "+f"(c[2]), "+f"(c[3])
        : "r"(a[0]), "r"(a[1]), "r"(a[2]), "r"(a[3]), "r"(b[0]), "r"(b[1]));
}

// ---------------------------------------------------------------------------
// GEMM: C[M,N] = A[M,K] @ W[N,K]^T (+bias). 128x128 tile, BK=16, 256 thr.
// Warp grid 2(m)x4(n); warp tile 64x32 = 4x4 m16n8 tiles.
// ---------------------------------------------------------------------------
#define GS 20   // smem k-stride (pad 16->20: conflict-free frag loads)

__global__ __launch_bounds__(256) void gemm_tf32(
    const float* __restrict__ A, const float* __restrict__ W,
    const float* __restrict__ bias, float* __restrict__ C,
    int M, int N, int K)
{
    __shared__ uint32_t As[128 * GS];
    __shared__ uint32_t Ws[128 * GS];

    const int t    = threadIdx.x;
    const int lane = t & 31, warp = t >> 5;
    const int g    = lane >> 2, tg = lane & 3;
    const int wm   = warp >> 2, wn = warp & 3;
    const int bm   = blockIdx.y * 128, bn = blockIdx.x * 128;
    const int row0 = t >> 2, c4 = (t & 3) * 4;

    const float* Ap = A + (size_t)(bm + row0) * K + c4;
    const float* Wp = W + (size_t)(bn + row0) * K + c4;

    float acc[4][4][4];
    #pragma unroll
    for (int i = 0; i < 4; i++)
        #pragma unroll
        for (int j = 0; j < 4; j++)
            #pragma unroll
            for (int r = 0; r < 4; r++) acc[i][j][r] = 0.f;

    for (int kb = 0; kb < K; kb += 16) {
        float4 a0 = *(const float4*)(Ap + kb);
        float4 a1 = *(const float4*)(Ap + (size_t)64 * K + kb);
        float4 w0 = *(const float4*)(Wp + kb);
        float4 w1 = *(const float4*)(Wp + (size_t)64 * K + kb);

        uint32_t* d;
        d = &As[row0 * GS + c4];
        d[0] = f2tf(a0.x); d[1] = f2tf(a0.y); d[2] = f2tf(a0.z); d[3] = f2tf(a0.w);
        d = &As[(row0 + 64) * GS + c4];
        d[0] = f2tf(a1.x); d[1] = f2tf(a1.y); d[2] = f2tf(a1.z); d[3] = f2tf(a1.w);
        d = &Ws[row0 * GS + c4];
        d[0] = f2tf(w0.x); d[1] = f2tf(w0.y); d[2] = f2tf(w0.z); d[3] = f2tf(w0.w);
        d = &Ws[(row0 + 64) * GS + c4];
        d[0] = f2tf(w1.x); d[1] = f2tf(w1.y); d[2] = f2tf(w1.z); d[3] = f2tf(w1.w);
        __syncthreads();

        #pragma unroll
        for (int ks = 0; ks < 16; ks += 8) {
            uint32_t af[4][4], bf[4][2];
            #pragma unroll
            for (int mt = 0; mt < 4; mt++) {
                int m0 = wm * 64 + mt * 16;
                af[mt][0] = As[(m0 + g) * GS + ks + tg];
                af[mt][1] = As[(m0 + g + 8) * GS + ks + tg];
                af[mt][2] = As[(m0 + g) * GS + ks + tg + 4];
                af[mt][3] = As[(m0 + g + 8) * GS + ks + tg + 4];
            }
            #pragma unroll
            for (int nt = 0; nt < 4; nt++) {
                int n0 = wn * 32 + nt * 8;
                bf[nt][0] = Ws[(n0 + g) * GS + ks + tg];
                bf[nt][1] = Ws[(n0 + g) * GS + ks + tg + 4];
            }
            #pragma unroll
            for (int mt = 0; mt < 4; mt++)
                #pragma unroll
                for (int nt = 0; nt < 4; nt++)
                    mma8(acc[mt][nt], af[mt], bf[nt]);
        }
        __syncthreads();
    }

    // epilogue
    #pragma unroll
    for (int nt = 0; nt < 4; nt++) {
        int n0 = bn + wn * 32 + nt * 8 + 2 * tg;
        float b0 = 0.f, b1 = 0.f;
        if (bias) { b0 = bias[n0]; b1 = bias[n0 + 1]; }
        #pragma unroll
        for (int mt = 0; mt < 4; mt++) {
            int r = bm + wm * 64 + mt * 16 + g;
            float2 v0 = make_float2(acc[mt][nt][0] + b0, acc[mt][nt][1] + b1);
            float2 v1 = make_float2(acc[mt][nt][2] + b0, acc[mt][nt][3] + b1);
            *(float2*)(C + (size_t)r * N + n0)       = v0;
            *(float2*)(C + (size_t)(r + 8) * N + n0) = v1;
        }
    }
}

// ---------------------------------------------------------------------------
// Flash attention, tf32 tensor cores. Block = 128 q-rows x one (b,h).
// 8 warps; warp w owns q-rows w*16..w*16+15. KV tile = 64.
// ---------------------------------------------------------------------------
#define QS 68   // smem row stride (words): conflict-free for all frag patterns
#define ATTN_SMEM_WORDS ((128 + 64 + 64 + 128) * QS)

__global__ __launch_bounds__(256) void attn_tf32()
{
    extern __shared__ uint32_t sm[];
    uint32_t* Qs = sm;                  // [128][QS]
    uint32_t* Ks = Qs + 128 * QS;       // [64][QS]
    uint32_t* Vs = Ks + 64 * QS;        // [64][QS]
    uint32_t* Ps = Vs + 64 * QS;        // [128][QS]

    const int t    = threadIdx.x;
    const int lane = t & 31, w = t >> 5;
    const int g    = lane >> 2, tg = lane & 3;
    const int qb   = blockIdx.x * 128;
    const int h    = blockIdx.y;
    const int b    = blockIdx.z;
    const int q0   = w * 16;
    const float SC = 0.125f * 1.44269504f;  // 1/sqrt(D) * log2(e)

    // load Q (scaled, tf32)
    {
        int row = t >> 1, cb = (t & 1) * 32;
        const float* src = g_qkv + (size_t)(b * NN + qb + row) * QKVN + h * DD + cb;
        #pragma unroll
        for (int i = 0; i < 8; i++) {
            float4 v = ((const float4*)src)[i];
            uint4 u = make_uint4(f2tf(v.x * SC), f2tf(v.y * SC),
                                 f2tf(v.z * SC), f2tf(v.w * SC));
            *(uint4*)&Qs[row * QS + cb + i * 4] = u;
        }
    }

    float o[8][4];
    #pragma unroll
    for (int i = 0; i < 8; i++)
        #pragma unroll
        for (int j = 0; j < 4; j++) o[i][j] = 0.f;
    float m0 = -INFINITY, m1 = -INFINITY, l0 = 0.f, l1 = 0.f;

    for (int kb = 0; kb < NN; kb += 64) {
        __syncthreads();   // prior iter's mma done before overwriting K/V
        {
            int row = t >> 2, cb2 = (t & 3) * 16;
            const float* ksrc = g_qkv + (size_t)(b * NN + kb + row) * QKVN + CC + h * DD + cb2;
            const float* vsrc = ksrc + CC;
            #pragma unroll
            for (int i = 0; i < 4; i++) {
                float4 v = ((const float4*)ksrc)[i];
                *(uint4*)&Ks[row * QS + cb2 + i * 4] =
                    make_uint4(f2tf(v.x), f2tf(v.y), f2tf(v.z), f2tf(v.w));
            }
            #pragma unroll
            for (int i = 0; i < 4; i++) {
                float4 v = ((const float4*)vsrc)[i];
                *(uint4*)&Vs[row * QS + cb2 + i * 4] =
                    make_uint4(f2tf(v.x), f2tf(v.y), f2tf(v.z), f2tf(v.w));
            }
        }
        __syncthreads();

        // ---- S = Q K^T (base-2 scaled) ----
        float s[8][4];
        #pragma unroll
        for (int i = 0; i < 8; i++)
            #pragma unroll
            for (int j = 0; j < 4; j++) s[i][j] = 0.f;

        #pragma unroll
        for (int ks = 0; ks < 64; ks += 8) {
            uint32_t af[4];
            af[0] = Qs[(q0 + g) * QS + ks + tg];
            af[1] = Qs[(q0 + g + 8) * QS + ks + tg];
            af[2] = Qs[(q0 + g) * QS + ks + tg + 4];
            af[3] = Qs[(q0 + g + 8) * QS + ks + tg + 4];
            #pragma unroll
            for (int jt = 0; jt < 8; jt++) {
                uint32_t bf[2];
                bf[0] = Ks[(jt * 8 + g) * QS + ks + tg];
                bf[1] = Ks[(jt * 8 + g) * QS + ks + tg + 4];
                mma8(s[jt], af, bf);
            }
        }

        // ---- online softmax (rows g and g+8; row spread over quad lanes) ----
        float mx0 = -INFINITY, mx1 = -INFINITY;
        #pragma unroll
        for (int jt = 0; jt < 8; jt++) {
            mx0 = fmaxf(mx0, fmaxf(s[jt][0], s[jt][1]));
            mx1 = fmaxf(mx1, fmaxf(s[jt][2], s[jt][3]));
        }
        mx0 = fmaxf(mx0, __shfl_xor_sync(0xffffffffu, mx0, 1));
        mx0 = fmaxf(mx0, __shfl_xor_sync(0xffffffffu, mx0, 2));
        mx1 = fmaxf(mx1, __shfl_xor_sync(0xffffffffu, mx1, 1));
        mx1 = fmaxf(mx1, __shfl_xor_sync(0xffffffffu, mx1, 2));

        float mn0 = fmaxf(m0, mx0), mn1 = fmaxf(m1, mx1);
        float cr0 = ex2(m0 - mn0), cr1 = ex2(m1 - mn1);
        m0 = mn0; m1 = mn1;

        float sum0 = 0.f, sum1 = 0.f;
        #pragma unroll
        for (int jt = 0; jt < 8; jt++) {
            s[jt][0] = ex2(s[jt][0] - mn0);
            s[jt][1] = ex2(s[jt][1] - mn0);
            s[jt][2] = ex2(s[jt][2] - mn1);
            s[jt][3] = ex2(s[jt][3] - mn1);
            sum0 += s[jt][0] + s[jt][1];
            sum1 += s[jt][2] + s[jt][3];
        }
        sum0 += __shfl_xor_sync(0xffffffffu, sum0, 1);
        sum0 += __shfl_xor_sync(0xffffffffu, sum0, 2);
        sum1 += __shfl_xor_sync(0xffffffffu, sum1, 1);
        sum1 += __shfl_xor_sync(0xffffffffu, sum1, 2);
        l0 = l0 * cr0 + sum0;
        l1 = l1 * cr1 + sum1;
        #pragma unroll
        for (int dt = 0; dt < 8; dt++) {
            o[dt][0] *= cr0; o[dt][1] *= cr0;
            o[dt][2] *= cr1; o[dt][3] *= cr1;
        }

        // ---- P -> smem (tf32); same-warp producer/consumer ----
        #pragma unroll
        for (int jt = 0; jt < 8; jt++) {
            Ps[(q0 + g) * QS + jt * 8 + 2 * tg]         = f2tf(s[jt][0]);
            Ps[(q0 + g) * QS + jt * 8 + 2 * tg + 1]     = f2tf(s[jt][1]);
            Ps[(q0 + g + 8) * QS + jt * 8 + 2 * tg]     = f2tf(s[jt][2]);
            Ps[(q0 + g + 8) * QS + jt * 8 + 2 * tg + 1] = f2tf(s[jt][3]);
        }
        __syncwarp();

        // ---- O += P V ----
        #pragma unroll
        for (int ks = 0; ks < 64; ks += 8) {
            uint32_t af[4];
            af[0] = Ps[(q0 + g) * QS + ks + tg];
            af[1] = Ps[(q0 + g + 8) * QS + ks + tg];
            af[2] = Ps[(q0 + g) * QS + ks + tg + 4];
            af[3] = Ps[(q0 + g + 8) * QS + ks + tg + 4];
            #pragma unroll
            for (int dt = 0; dt < 8; dt++) {
                uint32_t bf[2];
                bf[0] = Vs[(ks + tg) * QS + dt * 8 + g];
                bf[1] = Vs[(ks + tg + 4) * QS + dt * 8 + g];
                mma8(o[dt], af, bf);
            }
        }
    }

    // ---- normalize + write ----
    float i0 = 1.f / l0, i1 = 1.f / l1;
    #pragma unroll
    for (int dt = 0; dt < 8; dt++) {
        float* d0 = g_att + (size_t)(b * NN + qb + q0 + g) * CC + h * DD + dt * 8 + 2 * tg;
        float* d1 = g_att + (size_t)(b * NN + qb + q0 + g + 8) * CC + h * DD + dt * 8 + 2 * tg;
        *(float2*)d0 = make_float2(o[dt][0] * i0, o[dt][1] * i0);
        *(float2*)d1 = make_float2(o[dt][2] * i1, o[dt][3] * i1);
    }
}

// ---------------------------------------------------------------------------
extern "C" void kernel_launch(void* const* d_in, const int* in_sizes, int n_in,
                              void* d_out, int out_size)
{
    const float* x     = (const float*)d_in[0];
    const float* Wqkv  = (const float*)d_in[1];
    const float* Wproj = (const float*)d_in[2];
    const float* bproj = (const float*)d_in[3];
    float* out = (float*)d_out;

    float* qkv_ptr = nullptr;
    float* att_ptr = nullptr;
    cudaGetSymbolAddress((void**)&qkv_ptr, g_qkv);
    cudaGetSymbolAddress((void**)&att_ptr, g_att);

    static bool attr_set = false;
    if (!attr_set) {
        cudaFuncSetAttribute(attn_tf32, cudaFuncAttributeMaxDynamicSharedMemorySize,
                             ATTN_SMEM_WORDS * 4);
        attr_set = true;
    }

    // 1) QKV projection
    {
        dim3 grid(QKVN / 128, MTOK / 128);
        gemm_tf32<<<grid, 256>>>(x, Wqkv, nullptr, qkv_ptr, MTOK, QKVN, CC);
    }
    // 2) Attention
    {
        dim3 grid(NN / 128, HH, BB);
        attn_tf32<<<grid, 256, ATTN_SMEM_WORDS * 4>>>();
    }
    // 3) Output projection (+bias)
    {
        dim3 grid(CC / 128, MTOK / 128);
        gemm_tf32<<<grid, 256>>>(att_ptr, Wproj, bproj, out, MTOK, CC, CC);
    }
}